// round 9
// baseline (speedup 1.0000x reference)
#include <cuda_runtime.h>
#include <cstdint>

#define BATCH 2
#define SEQ   4096
#define EMB   768
#define NH    12
#define HD    64
#define M_ROWS (BATCH*SEQ)   /* 8192 */

__device__ float g_q  [(size_t)BATCH*NH*SEQ*HD];
__device__ float g_k  [(size_t)BATCH*NH*SEQ*HD];
__device__ float g_vt [(size_t)BATCH*NH*HD*SEQ];
__device__ float g_att[(size_t)M_ROWS*EMB];
__device__ float g_xr [(size_t)M_ROWS*EMB];
__device__ float g_wq [(size_t)3*EMB*EMB];
__device__ float g_wp [(size_t)EMB*EMB];

__device__ __forceinline__ float tf32r(float x){
    uint32_t u;
    asm("cvt.rna.tf32.f32 %0, %1;" : "=r"(u) : "f"(x));
    return __uint_as_float(u);
}

__device__ __forceinline__ void mma8(float c[4], const uint32_t a[4], const uint32_t b[2]){
    asm volatile(
      "mma.sync.aligned.m16n8k8.row.col.f32.tf32.tf32.f32 "
      "{%0,%1,%2,%3},{%4,%5,%6,%7},{%8,%9},{%0,%1,%2,%3};\n"
      : "+f"(c[0]), "+f"(c[1]), "+f"(c[2]), "+f"(c[3])
      : "r"(a[0]), "r"(a[1]), "r"(a[2]), "r"(a[3]), "r"(b[0]), "r"(b[1]));
}

__device__ __forceinline__ float ex2(float x){
    float y; asm("ex2.approx.ftz.f32 %0, %1;" : "=f"(y) : "f"(x)); return y;
}

__device__ __forceinline__ uint32_t smem_u32(const void* p){
    uint32_t a;
    asm("{ .reg .u64 t; cvta.to.shared.u64 t, %1; cvt.u32.u64 %0, t; }" : "=r"(a) : "l"(p));
    return a;
}

__device__ __forceinline__ void cpa16(uint32_t saddr, const float* g){
    asm volatile("cp.async.cg.shared.global [%0], [%1], 16;" :: "r"(saddr), "l"(g));
}
#define CP_COMMIT() asm volatile("cp.async.commit_group;" ::: "memory")
#define CP_WAIT0()  asm volatile("cp.async.wait_group 0;"  ::: "memory")
#define CP_WAIT1()  asm volatile("cp.async.wait_group 1;"  ::: "memory")
#define CP_WAIT2()  asm volatile("cp.async.wait_group 2;"  ::: "memory")

// pair-level XOR swizzle for 64-wide rows: conflict-free LDS.64 fragment loads
__device__ __forceinline__ int swz64(int row, int d){
    return (row<<6) + ((((d>>1) ^ ((row&7)<<2)) << 1) | (d&1));
}

// ======================= pre-round pass =======================================
__global__ __launch_bounds__(256) void round_tf32(const float* __restrict__ in,
                                                  float* __restrict__ out, int n4){
    int i = blockIdx.x*256 + threadIdx.x;
    if (i < n4){
        float4 v = ((const float4*)in)[i];
        v.x = tf32r(v.x); v.y = tf32r(v.y); v.z = tf32r(v.z); v.w = tf32r(v.w);
        ((float4*)out)[i] = v;
    }
}

// ======================= 3-stage pipelined tf32 GEMMs =========================
#define QSCALE 0.18033688011112042f   /* 0.125 * log2(e) */

__device__ __forceinline__ void scatter_qkv(int m, int n, float v){
    int which = n / EMB;
    int e = n - which*EMB;
    int h = e >> 6, d = e & 63;
    int b = m >> 12, s = m & (SEQ-1);
    if (which==0)      g_q [(((size_t)(b*NH+h))*SEQ + s)*HD + d] = tf32r(v * QSCALE);
    else if (which==1) g_k [(((size_t)(b*NH+h))*SEQ + s)*HD + d] = tf32r(v);
    else               g_vt[(((size_t)(b*NH+h))*HD  + d)*SEQ + s] = tf32r(v);
}

#define GCH 4608   /* floats per 128x36 buffer */
template<int MODE>
__global__ __launch_bounds__(256) void gemm_tf32(const float* __restrict__ A,
                                                 const float* __restrict__ B,
                                                 float* __restrict__ C,
                                                 const float* __restrict__ bias){
    const int K = EMB;
    extern __shared__ float sg[];   // A stages 0..2, B stages 0..2 (128x36 each)
    uint32_t sbase = smem_u32(sg);

    int tid  = threadIdx.x;
    int m0   = blockIdx.y*128, n0 = blockIdx.x*128;
    int lane = tid & 31, wid = tid >> 5;
    int wm   = (wid & 3) * 32, wn = (wid >> 2) * 64;
    int gid  = lane >> 2, tig = lane & 3;

    float acc[2][8][4];
    #pragma unroll
    for (int i=0;i<2;i++)
        #pragma unroll
        for (int nt=0;nt<8;nt++)
            #pragma unroll
            for (int j=0;j<4;j++) acc[i][nt][j]=0.f;

    int lr = tid >> 3;              // 0..31
    int lc = (tid & 7) * 4;         // 0..28
    auto issue = [&](int kk, int st){
        uint32_t oa = (uint32_t)st*GCH, ob = 3*GCH + (uint32_t)st*GCH;
        #pragma unroll
        for (int p=0;p<4;p++){
            int row = p*32 + lr;
            cpa16(sbase + (oa + row*36u + lc)*4u, A + (size_t)(m0+row)*K + kk + lc);
            cpa16(sbase + (ob + row*36u + lc)*4u, B + (size_t)(n0+row)*K + kk + lc);
        }
        CP_COMMIT();
    };

    issue(0, 0);
    issue(32, 1);
    for (int it = 0; it < 24; it++){
        int st = it % 3;
        if (it < 22){ issue((it+2)*32, (it+2)%3); CP_WAIT2(); }
        else if (it == 22){ CP_WAIT1(); }
        else { CP_WAIT0(); }
        __syncthreads();
        const float* sA = sg + st*GCH;
        const float* sB = sg + 3*GCH + st*GCH;
        #pragma unroll
        for (int k8=0;k8<4;k8++){
            int kc = k8*8;
            uint32_t a[2][4];
            #pragma unroll
            for (int i=0;i<2;i++){
                int r0 = wm + i*16 + gid;
                a[i][0] = __float_as_uint(sA[r0    *36 + kc+tig]);
                a[i][1] = __float_as_uint(sA[(r0+8)*36 + kc+tig]);
                a[i][2] = __float_as_uint(sA[r0    *36 + kc+tig+4]);
                a[i][3] = __float_as_uint(sA[(r0+8)*36 + kc+tig+4]);
            }
            #pragma unroll
            for (int nt=0;nt<8;nt++){
                int cn = wn + nt*8 + gid;
                uint32_t b[2];
                b[0] = __float_as_uint(sB[cn*36 + kc+tig]);
                b[1] = __float_as_uint(sB[cn*36 + kc+tig+4]);
                mma8(acc[0][nt], a[0], b);
                mma8(acc[1][nt], a[1], b);
            }
        }
        __syncthreads();
    }

    #pragma unroll
    for (int i=0;i<2;i++){
        int r0 = m0 + wm + i*16 + gid;
        #pragma unroll
        for (int nt=0;nt<8;nt++){
            int n = n0 + wn + nt*8 + tig*2;
            if (MODE==0){
                scatter_qkv(r0,   n,   acc[i][nt][0]);
                scatter_qkv(r0,   n+1, acc[i][nt][1]);
                scatter_qkv(r0+8, n,   acc[i][nt][2]);
                scatter_qkv(r0+8, n+1, acc[i][nt][3]);
            } else {
                C[(size_t)r0*EMB + n]       = acc[i][nt][0] + bias[n];
                C[(size_t)r0*EMB + n+1]     = acc[i][nt][1] + bias[n+1];
                C[(size_t)(r0+8)*EMB + n]   = acc[i][nt][2] + bias[n];
                C[(size_t)(r0+8)*EMB + n+1] = acc[i][nt][3] + bias[n+1];
            }
        }
    }
}

// ===================== flash attention: Q in smem, R=2, 2 CTAs/SM =============
// CTA: 256 threads = 8 warps x 32 q-rows. KT=64: K double-buffered, V single,
// Q resident in smem. 2 CTAs/SM -> 4 warps/SMSP.
#define OFF_Q  0
#define OFF_K0 16384
#define OFF_K1 20480
#define OFF_V  24576
#define SM_FLOATS 28672   /* 114688 B */

__global__ __launch_bounds__(256, 2) void attn_mma(){
    extern __shared__ float sm[];
    uint32_t sbase = smem_u32(sm);

    int tid = threadIdx.x, lane = tid & 31, wid = tid >> 5;
    int gid = lane >> 2, t = lane & 3;
    int qt = blockIdx.x, bh = blockIdx.y;
    int wrow = wid * 32;

    const float* Qp  = g_q  + (size_t)bh*SEQ*HD;
    const float* Kp  = g_k  + (size_t)bh*SEQ*HD;
    const float* Vtp = g_vt + (size_t)bh*HD*SEQ;

    int lrow = tid >> 2;               // 0..63
    int lcb  = (tid & 3) * 16;
    auto load_k = [&](int kt, int buf){
        uint32_t ok = (buf ? OFF_K1 : OFF_K0);
        const float* ks = Kp + (size_t)(kt*64 + lrow)*HD + lcb;
        #pragma unroll
        for (int i=0;i<4;i++){
            int col = lcb + i*4;
            cpa16(sbase + (uint32_t)(ok + swz64(lrow, col))*4u, ks + i*4);
        }
        CP_COMMIT();
    };
    auto load_v = [&](int kt){
        const float* vs = Vtp + (size_t)lrow*SEQ + kt*64 + lcb;
        #pragma unroll
        for (int i=0;i<4;i++){
            int col = lcb + i*4;
            cpa16(sbase + (uint32_t)(OFF_V + swz64(lrow, col))*4u, vs + i*4);
        }
        CP_COMMIT();
    };

    // prologue: Q tile (16384 floats) + K(0) in one group
    {
        #pragma unroll
        for (int i=0;i<16;i++){
            int c = i*256 + tid;
            int row = c >> 4, col = (c & 15) * 4;
            cpa16(sbase + (uint32_t)(OFF_Q + swz64(row, col))*4u,
                  Qp + (size_t)(qt*256 + row)*HD + col);
        }
        const float* ks = Kp + (size_t)lrow*HD + lcb;
        #pragma unroll
        for (int i=0;i<4;i++){
            int col = lcb + i*4;
            cpa16(sbase + (uint32_t)(OFF_K0 + swz64(lrow, col))*4u, ks + i*4);
        }
        CP_COMMIT();
    }

    float rs[4] = {0.f,0.f,0.f,0.f};
    float o[2][8][4];
    #pragma unroll
    for (int i=0;i<2;i++)
        #pragma unroll
        for (int dn=0;dn<8;dn++){ o[i][dn][0]=0;o[i][dn][1]=0;o[i][dn][2]=0;o[i][dn][3]=0; }

    for (int kt = 0; kt < SEQ/64; kt++){
        const float* sK = sm + ((kt&1) ? OFF_K1 : OFF_K0);
        const float* sV = sm + OFF_V;

        // issue V(kt) and K(kt+1); then drain everything up to K(kt)
        load_v(kt);
        if (kt < SEQ/64 - 1){ load_k(kt+1, (kt+1)&1); CP_WAIT2(); }
        else                { CP_WAIT1(); }
        __syncthreads();                     // K(kt) + Q visible to all

        #pragma unroll
        for (int c=0;c<2;c++){
            // S = Q K^T for 32 rows x 32 kv (Q fragments from smem)
            float s[2][4][4];
            #pragma unroll
            for (int i=0;i<2;i++)
                #pragma unroll
                for (int nt=0;nt<4;nt++){ s[i][nt][0]=0;s[i][nt][1]=0;s[i][nt][2]=0;s[i][nt][3]=0; }

            #pragma unroll
            for (int k8=0;k8<8;k8++){
                int kc = k8*8 + 2*t;
                float2 qa0 = *(const float2*)&sm[OFF_Q + swz64(wrow+gid,    kc)];
                float2 qb0 = *(const float2*)&sm[OFF_Q + swz64(wrow+gid+8,  kc)];
                float2 qa1 = *(const float2*)&sm[OFF_Q + swz64(wrow+gid+16, kc)];
                float2 qb1 = *(const float2*)&sm[OFF_Q + swz64(wrow+gid+24, kc)];
                uint32_t a0[4] = {__float_as_uint(qa0.x), __float_as_uint(qb0.x),
                                  __float_as_uint(qa0.y), __float_as_uint(qb0.y)};
                uint32_t a1[4] = {__float_as_uint(qa1.x), __float_as_uint(qb1.x),
                                  __float_as_uint(qa1.y), __float_as_uint(qb1.y)};
                #pragma unroll
                for (int nt=0;nt<4;nt++){
                    float2 kb = *(const float2*)&sK[swz64(c*32 + nt*8 + gid, kc)];
                    uint32_t b[2] = {__float_as_uint(kb.x), __float_as_uint(kb.y)};
                    mma8(s[0][nt], a0, b);
                    mma8(s[1][nt], a1, b);
                }
            }

            // exp2 + raw row sums
            #pragma unroll
            for (int i=0;i<2;i++)
                #pragma unroll
                for (int nt=0;nt<4;nt++){
                    float e0 = ex2(s[i][nt][0]);
                    float e1 = ex2(s[i][nt][1]);
                    float e2 = ex2(s[i][nt][2]);
                    float e3 = ex2(s[i][nt][3]);
                    rs[2*i]   += e0 + e1;
                    rs[2*i+1] += e2 + e3;
                    s[i][nt][0] = tf32r(e0); s[i][nt][1] = tf32r(e1);
                    s[i][nt][2] = tf32r(e2); s[i][nt][3] = tf32r(e3);
                }

            if (c == 0){
                // V(kt) must be visible before first PV
                if (kt < SEQ/64 - 1) CP_WAIT1(); else CP_WAIT0();
                __syncthreads();
            }

            // O += P V
            #pragma unroll
            for (int k8=0;k8<4;k8++){
                uint32_t a0[4] = {__float_as_uint(s[0][k8][0]), __float_as_uint(s[0][k8][2]),
                                  __float_as_uint(s[0][k8][1]), __float_as_uint(s[0][k8][3])};
                uint32_t a1[4] = {__float_as_uint(s[1][k8][0]), __float_as_uint(s[1][k8][2]),
                                  __float_as_uint(s[1][k8][1]), __float_as_uint(s[1][k8][3])};
                int kv0 = c*32 + k8*8 + 2*t;
                #pragma unroll
                for (int dn=0;dn<8;dn++){
                    float2 vb = *(const float2*)&sV[swz64(dn*8 + gid, kv0)];
                    uint32_t b[2] = {__float_as_uint(vb.x), __float_as_uint(vb.y)};
                    mma8(o[0][dn], a0, b);
                    mma8(o[1][dn], a1, b);
                }
            }
        }
        __syncthreads();   // V + K(kt+1) buffers free to overwrite next iter
    }

    #pragma unroll
    for (int k=0;k<4;k++){
        rs[k] += __shfl_xor_sync(0xffffffffu, rs[k], 1);
        rs[k] += __shfl_xor_sync(0xffffffffu, rs[k], 2);
    }

    // epilogue -> g_att in [B,S,E], pre-rounded to tf32 for the proj GEMM
    float il[4] = {1.f/rs[0], 1.f/rs[1], 1.f/rs[2], 1.f/rs[3]};
    int b = bh / NH, h = bh % NH;
    int r0 = qt*256 + wrow + gid;
    float* p0 = g_att + ((size_t)b*SEQ + r0)*EMB + h*HD;
    #pragma unroll
    for (int i=0;i<2;i++){
        #pragma unroll
        for (int dn=0;dn<8;dn++){
            int d = dn*8 + 2*t;
            float2 w0; w0.x = tf32r(o[i][dn][0]*il[2*i]);   w0.y = tf32r(o[i][dn][1]*il[2*i]);
            float2 w1; w1.x = tf32r(o[i][dn][2]*il[2*i+1]); w1.y = tf32r(o[i][dn][3]*il[2*i+1]);
            *(float2*)&p0[(size_t)(i*16  )*EMB + d] = w0;
            *(float2*)&p0[(size_t)(i*16+8)*EMB + d] = w1;
        }
    }
}

extern "C" void kernel_launch(void* const* d_in, const int* in_sizes, int n_in,
                              void* d_out, int out_size){
    (void)in_sizes; (void)n_in; (void)out_size;
    const float* x     = (const float*)d_in[0];
    const float* Wqkv  = (const float*)d_in[1];
    const float* Wproj = (const float*)d_in[2];
    const float* bproj = (const float*)d_in[3];
    float* out = (float*)d_out;

    float *d_xr, *d_wq, *d_wp, *d_att;
    cudaGetSymbolAddress((void**)&d_xr,  g_xr);
    cudaGetSymbolAddress((void**)&d_wq,  g_wq);
    cudaGetSymbolAddress((void**)&d_wp,  g_wp);
    cudaGetSymbolAddress((void**)&d_att, g_att);

    const int attn_smem = SM_FLOATS * (int)sizeof(float);  // 114688 B
    const int gemm_smem = 6*GCH * (int)sizeof(float);      // 110592 B
    cudaFuncSetAttribute(attn_mma,     cudaFuncAttributeMaxDynamicSharedMemorySize, attn_smem);
    cudaFuncSetAttribute(gemm_tf32<0>, cudaFuncAttributeMaxDynamicSharedMemorySize, gemm_smem);
    cudaFuncSetAttribute(gemm_tf32<1>, cudaFuncAttributeMaxDynamicSharedMemorySize, gemm_smem);

    // 0) pre-round inputs to tf32
    round_tf32<<<(M_ROWS*EMB/4 + 255)/256, 256>>>(x,     d_xr, M_ROWS*EMB/4);
    round_tf32<<<(3*EMB*EMB/4  + 255)/256, 256>>>(Wqkv,  d_wq, 3*EMB*EMB/4);
    round_tf32<<<(EMB*EMB/4    + 255)/256, 256>>>(Wproj, d_wp, EMB*EMB/4);

    // 1) QKV projection -> tf32-rounded Q/K (Q pre-scaled) and transposed V
    gemm_tf32<0><<<dim3(3*EMB/128, M_ROWS/128), 256, gemm_smem>>>(d_xr, d_wq, nullptr, nullptr);
    // 2) flash attention (Q in smem, R=2, 2 CTAs/SM)
    attn_mma<<<dim3(SEQ/256, BATCH*NH), 256, attn_smem>>>();
    // 3) output projection + bias
    gemm_tf32<1><<<dim3(EMB/128, M_ROWS/128), 256, gemm_smem>>>(d_att, d_wp, out, bproj);
}

// round 10
// speedup vs baseline: 1.7949x; 1.7949x over previous
#include <cuda_runtime.h>
#include <cuda_fp16.h>
#include <cstdint>

#define BATCH 2
#define SEQ   4096
#define EMB   768
#define NH    12
#define HD    64
#define M_ROWS (BATCH*SEQ)   /* 8192 */

// Q/K in [B,H,S,D] fp16 (Q pre-scaled by 0.125*log2e), V transposed [B,H,D,S] fp16.
__device__ __half g_q [(size_t)BATCH*NH*SEQ*HD];
__device__ __half g_k [(size_t)BATCH*NH*SEQ*HD];
__device__ __half g_vt[(size_t)BATCH*NH*HD*SEQ];
__device__ float  g_att[(size_t)M_ROWS*EMB];
__device__ float  g_xr [(size_t)M_ROWS*EMB];
__device__ float  g_wq [(size_t)3*EMB*EMB];
__device__ float  g_wp [(size_t)EMB*EMB];

__device__ __forceinline__ float tf32r(float x){
    uint32_t u;
    asm("cvt.rna.tf32.f32 %0, %1;" : "=r"(u) : "f"(x));
    return __uint_as_float(u);
}

__device__ __forceinline__ void mma8(float c[4], const uint32_t a[4], const uint32_t b[2]){
    asm volatile(
      "mma.sync.aligned.m16n8k8.row.col.f32.tf32.tf32.f32 "
      "{%0,%1,%2,%3},{%4,%5,%6,%7},{%8,%9},{%0,%1,%2,%3};\n"
      : "+f"(c[0]), "+f"(c[1]), "+f"(c[2]), "+f"(c[3])
      : "r"(a[0]), "r"(a[1]), "r"(a[2]), "r"(a[3]), "r"(b[0]), "r"(b[1]));
}

__device__ __forceinline__ void mma16(float c[4], const uint32_t a[4], const uint32_t b[2]){
    asm volatile(
      "mma.sync.aligned.m16n8k16.row.col.f32.f16.f16.f32 "
      "{%0,%1,%2,%3},{%4,%5,%6,%7},{%8,%9},{%0,%1,%2,%3};\n"
      : "+f"(c[0]), "+f"(c[1]), "+f"(c[2]), "+f"(c[3])
      : "r"(a[0]), "r"(a[1]), "r"(a[2]), "r"(a[3]), "r"(b[0]), "r"(b[1]));
}

__device__ __forceinline__ float ex2(float x){
    float y; asm("ex2.approx.ftz.f32 %0, %1;" : "=f"(y) : "f"(x)); return y;
}

__device__ __forceinline__ uint32_t h2pack(float lo, float hi){
    __half2 h = __floats2half2_rn(lo, hi);
    return *reinterpret_cast<uint32_t*>(&h);
}

__device__ __forceinline__ uint32_t smem_u32(const void* p){
    uint32_t a;
    asm("{ .reg .u64 t; cvta.to.shared.u64 t, %1; cvt.u32.u64 %0, t; }" : "=r"(a) : "l"(p));
    return a;
}

__device__ __forceinline__ void cpa16(uint32_t saddr, const void* g){
    asm volatile("cp.async.cg.shared.global [%0], [%1], 16;" :: "r"(saddr), "l"(g));
}
#define CP_COMMIT() asm volatile("cp.async.commit_group;" ::: "memory")
#define CP_WAIT0()  asm volatile("cp.async.wait_group 0;"  ::: "memory")
#define CP_WAIT1()  asm volatile("cp.async.wait_group 1;"  ::: "memory")
#define CP_WAIT2()  asm volatile("cp.async.wait_group 2;"  ::: "memory")

// ======================= pre-round pass =======================================
__global__ __launch_bounds__(256) void round_tf32(const float* __restrict__ in,
                                                  float* __restrict__ out, int n4){
    int i = blockIdx.x*256 + threadIdx.x;
    if (i < n4){
        float4 v = ((const float4*)in)[i];
        v.x = tf32r(v.x); v.y = tf32r(v.y); v.z = tf32r(v.z); v.w = tf32r(v.w);
        ((float4*)out)[i] = v;
    }
}

// ======================= 3-stage pipelined tf32 GEMMs =========================
#define QSCALE 0.18033688011112042f   /* 0.125 * log2(e) */

__device__ __forceinline__ void scatter2(int m, int n, float v0, float v1){
    int which = n / EMB;
    int e = n - which*EMB;
    int h = e >> 6, d = e & 63;      // d even (n = base + tig*2)
    int b = m >> 12, s = m & (SEQ-1);
    size_t bh = (size_t)(b*NH + h);
    if (which==0){
        *(__half2*)&g_q[(bh*SEQ + s)*HD + d] = __floats2half2_rn(v0*QSCALE, v1*QSCALE);
    } else if (which==1){
        *(__half2*)&g_k[(bh*SEQ + s)*HD + d] = __floats2half2_rn(v0, v1);
    } else {
        g_vt[(bh*HD + d  )*SEQ + s] = __float2half_rn(v0);
        g_vt[(bh*HD + d+1)*SEQ + s] = __float2half_rn(v1);
    }
}

#define GCH 4608   /* floats per 128x36 buffer */
template<int MODE>
__global__ __launch_bounds__(256) void gemm_tf32(const float* __restrict__ A,
                                                 const float* __restrict__ B,
                                                 float* __restrict__ C,
                                                 const float* __restrict__ bias){
    const int K = EMB;
    extern __shared__ float sg[];   // A stages 0..2, B stages 0..2 (128x36 each)
    uint32_t sbase = smem_u32(sg);

    int tid  = threadIdx.x;
    int m0   = blockIdx.y*128, n0 = blockIdx.x*128;
    int lane = tid & 31, wid = tid >> 5;
    int wm   = (wid & 3) * 32, wn = (wid >> 2) * 64;
    int gid  = lane >> 2, tig = lane & 3;

    float acc[2][8][4];
    #pragma unroll
    for (int i=0;i<2;i++)
        #pragma unroll
        for (int nt=0;nt<8;nt++)
            #pragma unroll
            for (int j=0;j<4;j++) acc[i][nt][j]=0.f;

    int lr = tid >> 3;
    int lc = (tid & 7) * 4;
    auto issue = [&](int kk, int st){
        uint32_t oa = (uint32_t)st*GCH, ob = 3*GCH + (uint32_t)st*GCH;
        #pragma unroll
        for (int p=0;p<4;p++){
            int row = p*32 + lr;
            cpa16(sbase + (oa + row*36u + lc)*4u, A + (size_t)(m0+row)*K + kk + lc);
            cpa16(sbase + (ob + row*36u + lc)*4u, B + (size_t)(n0+row)*K + kk + lc);
        }
        CP_COMMIT();
    };

    issue(0, 0);
    issue(32, 1);
    for (int it = 0; it < 24; it++){
        int st = it % 3;
        if (it < 22){ issue((it+2)*32, (it+2)%3); CP_WAIT2(); }
        else if (it == 22){ CP_WAIT1(); }
        else { CP_WAIT0(); }
        __syncthreads();
        const float* sA = sg + st*GCH;
        const float* sB = sg + 3*GCH + st*GCH;
        #pragma unroll
        for (int k8=0;k8<4;k8++){
            int kc = k8*8;
            uint32_t a[2][4];
            #pragma unroll
            for (int i=0;i<2;i++){
                int r0 = wm + i*16 + gid;
                a[i][0] = __float_as_uint(sA[r0    *36 + kc+tig]);
                a[i][1] = __float_as_uint(sA[(r0+8)*36 + kc+tig]);
                a[i][2] = __float_as_uint(sA[r0    *36 + kc+tig+4]);
                a[i][3] = __float_as_uint(sA[(r0+8)*36 + kc+tig+4]);
            }
            #pragma unroll
            for (int nt=0;nt<8;nt++){
                int cn = wn + nt*8 + gid;
                uint32_t b[2];
                b[0] = __float_as_uint(sB[cn*36 + kc+tig]);
                b[1] = __float_as_uint(sB[cn*36 + kc+tig+4]);
                mma8(acc[0][nt], a[0], b);
                mma8(acc[1][nt], a[1], b);
            }
        }
        __syncthreads();
    }

    #pragma unroll
    for (int i=0;i<2;i++){
        int r0 = m0 + wm + i*16 + gid;
        #pragma unroll
        for (int nt=0;nt<8;nt++){
            int n = n0 + wn + nt*8 + tig*2;
            if (MODE==0){
                scatter2(r0,   n, acc[i][nt][0], acc[i][nt][1]);
                scatter2(r0+8, n, acc[i][nt][2], acc[i][nt][3]);
            } else {
                C[(size_t)r0*EMB + n]       = acc[i][nt][0] + bias[n];
                C[(size_t)r0*EMB + n+1]     = acc[i][nt][1] + bias[n+1];
                C[(size_t)(r0+8)*EMB + n]   = acc[i][nt][2] + bias[n];
                C[(size_t)(r0+8)*EMB + n+1] = acc[i][nt][3] + bias[n+1];
            }
        }
    }
}

// ===================== flash attention: fp16 mma, 512 thr, Q in regs ==========
// CTA: 256 q rows, 16 warps x 16 rows. KT=64, K/V double-buffered fp16.
// Tiles: 64 rows x 72 halfs (stride 72 -> conflict-free LDS.32, 16B cp.async ok)
#define TSTR   72
#define OFF_K0 0
#define OFF_K1 4608
#define OFF_V0 9216
#define OFF_V1 13824
#define SM_HALFS 18432   /* 36864 B */

__global__ __launch_bounds__(512, 1) void attn_mma(){
    extern __shared__ __half smh[];
    uint32_t sbase = smem_u32(smh);

    int tid = threadIdx.x, lane = tid & 31, wid = tid >> 5;
    int gid = lane >> 2, t = lane & 3;
    int qt = blockIdx.x, bh = blockIdx.y;
    int wrow = wid * 16;

    const __half* Qp  = g_q  + (size_t)bh*SEQ*HD;
    const __half* Kp  = g_k  + (size_t)bh*SEQ*HD;
    const __half* Vtp = g_vt + (size_t)bh*HD*SEQ;

    // 512 threads: 1 x 16B per tile each (64 rows x 128B data)
    int lrow = tid >> 3;               // 0..63
    int lcb  = (tid & 7) * 8;          // half offset within row
    auto load_kv = [&](int kt, int buf){
        uint32_t ok = (buf ? OFF_K1 : OFF_K0);
        uint32_t ov = (buf ? OFF_V1 : OFF_V0);
        cpa16(sbase + (ok + (uint32_t)lrow*TSTR + lcb)*2u,
              Kp + (size_t)(kt*64 + lrow)*HD + lcb);
        cpa16(sbase + (ov + (uint32_t)lrow*TSTR + lcb)*2u,
              Vtp + (size_t)lrow*SEQ + kt*64 + lcb);
    };

    // Q fragments -> registers (fp16 m16n8k16 A-frag layout), 16 rows/warp
    uint32_t qf[4][4];
    {
        const __half* q0 = Qp + (size_t)(qt*256 + wrow)*HD;
        #pragma unroll
        for (int j=0;j<4;j++){
            int c = j*16 + 2*t;
            qf[j][0] = *(const uint32_t*)(q0 + (size_t)(gid  )*HD + c);
            qf[j][1] = *(const uint32_t*)(q0 + (size_t)(gid+8)*HD + c);
            qf[j][2] = *(const uint32_t*)(q0 + (size_t)(gid  )*HD + c + 8);
            qf[j][3] = *(const uint32_t*)(q0 + (size_t)(gid+8)*HD + c + 8);
        }
    }

    load_kv(0, 0);
    CP_COMMIT(); CP_WAIT0();
    __syncthreads();

    float rs[2] = {0.f, 0.f};
    float o[8][4];
    #pragma unroll
    for (int dn=0;dn<8;dn++){ o[dn][0]=0;o[dn][1]=0;o[dn][2]=0;o[dn][3]=0; }

    for (int kt = 0; kt < SEQ/64; kt++){
        int cur = kt & 1;
        if (kt < SEQ/64 - 1){ load_kv(kt+1, cur^1); CP_COMMIT(); }

        const __half* sK = smh + (cur ? OFF_K1 : OFF_K0);
        const __half* sV = smh + (cur ? OFF_V1 : OFF_V0);

        #pragma unroll
        for (int c=0;c<2;c++){
            int cb = c*32;
            // S = Q K^T : 16 rows x 32 kv (4 n-tiles, 4 k16 chunks over d)
            float s[4][4];
            #pragma unroll
            for (int nt=0;nt<4;nt++){ s[nt][0]=0;s[nt][1]=0;s[nt][2]=0;s[nt][3]=0; }
            #pragma unroll
            for (int j=0;j<4;j++){
                int kc = j*16 + 2*t;
                #pragma unroll
                for (int nt=0;nt<4;nt++){
                    const __half* kr = sK + (cb + nt*8 + gid)*TSTR + kc;
                    uint32_t b[2] = { *(const uint32_t*)kr, *(const uint32_t*)(kr+8) };
                    mma16(s[nt], qf[j], b);
                }
            }

            // exp2 + raw row sums, pack P into fp16 A-frags (no shuffles)
            #pragma unroll
            for (int nt=0;nt<4;nt++){
                s[nt][0] = ex2(s[nt][0]); s[nt][1] = ex2(s[nt][1]);
                s[nt][2] = ex2(s[nt][2]); s[nt][3] = ex2(s[nt][3]);
                rs[0] += s[nt][0] + s[nt][1];
                rs[1] += s[nt][2] + s[nt][3];
            }
            uint32_t pa[2][4];
            #pragma unroll
            for (int jj=0;jj<2;jj++){
                pa[jj][0] = h2pack(s[2*jj  ][0], s[2*jj  ][1]);
                pa[jj][1] = h2pack(s[2*jj  ][2], s[2*jj  ][3]);
                pa[jj][2] = h2pack(s[2*jj+1][0], s[2*jj+1][1]);
                pa[jj][3] = h2pack(s[2*jj+1][2], s[2*jj+1][3]);
            }

            // O += P V : Vt d-major, kv is the k dim
            #pragma unroll
            for (int jj=0;jj<2;jj++){
                int kv0 = cb + jj*16 + 2*t;
                #pragma unroll
                for (int dn=0;dn<8;dn++){
                    const __half* vr = sV + (dn*8 + gid)*TSTR + kv0;
                    uint32_t b[2] = { *(const uint32_t*)vr, *(const uint32_t*)(vr+8) };
                    mma16(o[dn], pa[jj], b);
                }
            }
        }

        CP_WAIT0();
        __syncthreads();
    }

    // reduce row sums across lane quads (deferred; sums are linear)
    #pragma unroll
    for (int k=0;k<2;k++){
        rs[k] += __shfl_xor_sync(0xffffffffu, rs[k], 1);
        rs[k] += __shfl_xor_sync(0xffffffffu, rs[k], 2);
    }

    // epilogue -> g_att in [B,S,E], pre-rounded to tf32 for the proj GEMM
    float il0 = 1.f/rs[0], il1 = 1.f/rs[1];
    int b = bh / NH, h = bh % NH;
    int r0 = qt*256 + wrow + gid;
    float* p0 = g_att + ((size_t)b*SEQ + r0)*EMB + h*HD;
    float* p1 = p0 + (size_t)8*EMB;
    #pragma unroll
    for (int dn=0;dn<8;dn++){
        int d = dn*8 + 2*t;
        float2 w0; w0.x = tf32r(o[dn][0]*il0); w0.y = tf32r(o[dn][1]*il0);
        float2 w1; w1.x = tf32r(o[dn][2]*il1); w1.y = tf32r(o[dn][3]*il1);
        *(float2*)&p0[d] = w0;
        *(float2*)&p1[d] = w1;
    }
}

extern "C" void kernel_launch(void* const* d_in, const int* in_sizes, int n_in,
                              void* d_out, int out_size){
    (void)in_sizes; (void)n_in; (void)out_size;
    const float* x     = (const float*)d_in[0];
    const float* Wqkv  = (const float*)d_in[1];
    const float* Wproj = (const float*)d_in[2];
    const float* bproj = (const float*)d_in[3];
    float* out = (float*)d_out;

    float *d_xr, *d_wq, *d_wp, *d_att;
    cudaGetSymbolAddress((void**)&d_xr,  g_xr);
    cudaGetSymbolAddress((void**)&d_wq,  g_wq);
    cudaGetSymbolAddress((void**)&d_wp,  g_wp);
    cudaGetSymbolAddress((void**)&d_att, g_att);

    const int attn_smem = SM_HALFS * (int)sizeof(__half);  // 36864 B
    const int gemm_smem = 6*GCH * (int)sizeof(float);      // 110592 B
    cudaFuncSetAttribute(attn_mma,     cudaFuncAttributeMaxDynamicSharedMemorySize, attn_smem);
    cudaFuncSetAttribute(gemm_tf32<0>, cudaFuncAttributeMaxDynamicSharedMemorySize, gemm_smem);
    cudaFuncSetAttribute(gemm_tf32<1>, cudaFuncAttributeMaxDynamicSharedMemorySize, gemm_smem);

    // 0) pre-round inputs to tf32 (GEMM operands stay fp32/tf32)
    round_tf32<<<(M_ROWS*EMB/4 + 255)/256, 256>>>(x,     d_xr, M_ROWS*EMB/4);
    round_tf32<<<(3*EMB*EMB/4  + 255)/256, 256>>>(Wqkv,  d_wq, 3*EMB*EMB/4);
    round_tf32<<<(EMB*EMB/4    + 255)/256, 256>>>(Wproj, d_wp, EMB*EMB/4);

    // 1) QKV projection -> fp16 Q/K (Q pre-scaled) and fp16 transposed V
    gemm_tf32<0><<<dim3(3*EMB/128, M_ROWS/128), 256, gemm_smem>>>(d_xr, d_wq, nullptr, nullptr);
    // 2) flash attention (fp16 mma m16n8k16, Q-in-regs)
    attn_mma<<<dim3(SEQ/256, BATCH*NH), 512, attn_smem>>>();
    // 3) output projection + bias
    gemm_tf32<1><<<dim3(EMB/128, M_ROWS/128), 256, gemm_smem>>>(d_att, d_wp, out, bproj);
}

// round 11
// speedup vs baseline: 2.0719x; 1.1543x over previous
#include <cuda_runtime.h>
#include <cuda_fp16.h>
#include <cstdint>

#define BATCH 2
#define SEQ   4096
#define EMB   768
#define NH    12
#define HD    64
#define M_ROWS (BATCH*SEQ)   /* 8192 */

// fp16 operands everywhere; fp32 accumulation. Q pre-scaled by 0.125*log2e.
__device__ __half g_q  [(size_t)BATCH*NH*SEQ*HD];
__device__ __half g_k  [(size_t)BATCH*NH*SEQ*HD];
__device__ __half g_vt [(size_t)BATCH*NH*HD*SEQ];
__device__ __half g_att[(size_t)M_ROWS*EMB];
__device__ __half g_xh [(size_t)M_ROWS*EMB];
__device__ __half g_wqh[(size_t)3*EMB*EMB];
__device__ __half g_wph[(size_t)EMB*EMB];

__device__ __forceinline__ void mma16(float c[4], const uint32_t a[4], const uint32_t b[2]){
    asm volatile(
      "mma.sync.aligned.m16n8k16.row.col.f32.f16.f16.f32 "
      "{%0,%1,%2,%3},{%4,%5,%6,%7},{%8,%9},{%0,%1,%2,%3};\n"
      : "+f"(c[0]), "+f"(c[1]), "+f"(c[2]), "+f"(c[3])
      : "r"(a[0]), "r"(a[1]), "r"(a[2]), "r"(a[3]), "r"(b[0]), "r"(b[1]));
}

__device__ __forceinline__ float ex2(float x){
    float y; asm("ex2.approx.ftz.f32 %0, %1;" : "=f"(y) : "f"(x)); return y;
}

__device__ __forceinline__ uint32_t h2pack(float lo, float hi){
    __half2 h = __floats2half2_rn(lo, hi);
    return *reinterpret_cast<uint32_t*>(&h);
}

__device__ __forceinline__ uint32_t smem_u32(const void* p){
    uint32_t a;
    asm("{ .reg .u64 t; cvta.to.shared.u64 t, %1; cvt.u32.u64 %0, t; }" : "=r"(a) : "l"(p));
    return a;
}

__device__ __forceinline__ void cpa16(uint32_t saddr, const void* g){
    asm volatile("cp.async.cg.shared.global [%0], [%1], 16;" :: "r"(saddr), "l"(g));
}
#define CP_COMMIT() asm volatile("cp.async.commit_group;" ::: "memory")
#define CP_WAIT0()  asm volatile("cp.async.wait_group 0;"  ::: "memory")
#define CP_WAIT1()  asm volatile("cp.async.wait_group 1;"  ::: "memory")
#define CP_WAIT2()  asm volatile("cp.async.wait_group 2;"  ::: "memory")

// ======================= fp32 -> fp16 pre-convert pass ========================
__global__ __launch_bounds__(256) void to_fp16(const float* __restrict__ in,
                                               __half* __restrict__ out, int n4){
    int i = blockIdx.x*256 + threadIdx.x;
    if (i < n4){
        float4 v = ((const float4*)in)[i];
        uint2 o;
        o.x = h2pack(v.x, v.y);
        o.y = h2pack(v.z, v.w);
        ((uint2*)out)[i] = o;
    }
}

// ======================= 3-stage pipelined fp16 GEMMs =========================
#define QSCALE 0.18033688011112042f   /* 0.125 * log2(e) */

__device__ __forceinline__ void scatter2(int m, int n, float v0, float v1){
    int which = n / EMB;
    int e = n - which*EMB;
    int h = e >> 6, d = e & 63;      // d even
    int b = m >> 12, s = m & (SEQ-1);
    size_t bh = (size_t)(b*NH + h);
    if (which==0){
        *(__half2*)&g_q[(bh*SEQ + s)*HD + d] = __floats2half2_rn(v0*QSCALE, v1*QSCALE);
    } else if (which==1){
        *(__half2*)&g_k[(bh*SEQ + s)*HD + d] = __floats2half2_rn(v0, v1);
    } else {
        g_vt[(bh*HD + d  )*SEQ + s] = __float2half_rn(v0);
        g_vt[(bh*HD + d+1)*SEQ + s] = __float2half_rn(v1);
    }
}

// smem tile: 128 rows x 40 halfs (32 data + 8 pad). stride 40h = 80B:
// fragment quad pattern (gid*80 + t*4) mod 128B is conflict-free.
#define GSTR 40
#define GCH  5120   /* halfs per 128x40 buffer */

template<int MODE>
__global__ __launch_bounds__(256) void gemm_fp16(const __half* __restrict__ A,
                                                 const __half* __restrict__ B,
                                                 float* __restrict__ C,
                                                 const float* __restrict__ bias){
    const int K = EMB;
    extern __shared__ __half sg[];   // A stages 0..2, B stages 0..2
    uint32_t sbase = smem_u32(sg);

    int tid  = threadIdx.x;
    int m0   = blockIdx.y*128, n0 = blockIdx.x*128;
    int lane = tid & 31, wid = tid >> 5;
    int wm   = (wid & 3) * 32, wn = (wid >> 2) * 64;
    int gid  = lane >> 2, t = lane & 3;

    float acc[2][8][4];
    #pragma unroll
    for (int i=0;i<2;i++)
        #pragma unroll
        for (int nt=0;nt<8;nt++)
            #pragma unroll
            for (int j=0;j<4;j++) acc[i][nt][j]=0.f;

    int lr = tid >> 1;              // 0..127 (row)
    int lc = (tid & 1) * 16;        // half offset 0/16
    auto issue = [&](int kk, int st){
        uint32_t oa = (uint32_t)st*GCH, ob = 3*GCH + (uint32_t)st*GCH;
        const __half* as = A + (size_t)(m0+lr)*K + kk + lc;
        const __half* bs = B + (size_t)(n0+lr)*K + kk + lc;
        uint32_t da = sbase + (oa + (uint32_t)lr*GSTR + lc)*2u;
        uint32_t db = sbase + (ob + (uint32_t)lr*GSTR + lc)*2u;
        cpa16(da,      as);
        cpa16(da + 16, as + 8);
        cpa16(db,      bs);
        cpa16(db + 16, bs + 8);
        CP_COMMIT();
    };

    issue(0, 0);
    issue(32, 1);
    for (int it = 0; it < 24; it++){
        int st = it % 3;
        if (it < 22){ issue((it+2)*32, (it+2)%3); CP_WAIT2(); }
        else if (it == 22){ CP_WAIT1(); }
        else { CP_WAIT0(); }
        __syncthreads();
        const __half* sA = sg + st*GCH;
        const __half* sB = sg + 3*GCH + st*GCH;
        #pragma unroll
        for (int ks=0;ks<2;ks++){
            int kc = ks*16 + 2*t;
            uint32_t a[2][4];
            #pragma unroll
            for (int i=0;i<2;i++){
                int r0 = wm + i*16 + gid;
                a[i][0] = *(const uint32_t*)&sA[r0    *GSTR + kc];
                a[i][1] = *(const uint32_t*)&sA[(r0+8)*GSTR + kc];
                a[i][2] = *(const uint32_t*)&sA[r0    *GSTR + kc + 8];
                a[i][3] = *(const uint32_t*)&sA[(r0+8)*GSTR + kc + 8];
            }
            #pragma unroll
            for (int nt=0;nt<8;nt++){
                int cn = wn + nt*8 + gid;
                uint32_t b[2];
                b[0] = *(const uint32_t*)&sB[cn*GSTR + kc];
                b[1] = *(const uint32_t*)&sB[cn*GSTR + kc + 8];
                mma16(acc[0][nt], a[0], b);
                mma16(acc[1][nt], a[1], b);
            }
        }
        __syncthreads();
    }

    #pragma unroll
    for (int i=0;i<2;i++){
        int r0 = m0 + wm + i*16 + gid;
        #pragma unroll
        for (int nt=0;nt<8;nt++){
            int n = n0 + wn + nt*8 + t*2;
            if (MODE==0){
                scatter2(r0,   n, acc[i][nt][0], acc[i][nt][1]);
                scatter2(r0+8, n, acc[i][nt][2], acc[i][nt][3]);
            } else {
                C[(size_t)r0*EMB + n]       = acc[i][nt][0] + bias[n];
                C[(size_t)r0*EMB + n+1]     = acc[i][nt][1] + bias[n+1];
                C[(size_t)(r0+8)*EMB + n]   = acc[i][nt][2] + bias[n];
                C[(size_t)(r0+8)*EMB + n+1] = acc[i][nt][3] + bias[n+1];
            }
        }
    }
}

// ===================== flash attention: fp16 mma, 512 thr, Q in regs ==========
#define TSTR   72
#define OFF_K0 0
#define OFF_K1 4608
#define OFF_V0 9216
#define OFF_V1 13824
#define SM_HALFS 18432   /* 36864 B */

__global__ __launch_bounds__(512, 1) void attn_mma(){
    extern __shared__ __half smh[];
    uint32_t sbase = smem_u32(smh);

    int tid = threadIdx.x, lane = tid & 31, wid = tid >> 5;
    int gid = lane >> 2, t = lane & 3;
    int qt = blockIdx.x, bh = blockIdx.y;
    int wrow = wid * 16;

    const __half* Qp  = g_q  + (size_t)bh*SEQ*HD;
    const __half* Kp  = g_k  + (size_t)bh*SEQ*HD;
    const __half* Vtp = g_vt + (size_t)bh*HD*SEQ;

    int lrow = tid >> 3;               // 0..63
    int lcb  = (tid & 7) * 8;
    auto load_kv = [&](int kt, int buf){
        uint32_t ok = (buf ? OFF_K1 : OFF_K0);
        uint32_t ov = (buf ? OFF_V1 : OFF_V0);
        cpa16(sbase + (ok + (uint32_t)lrow*TSTR + lcb)*2u,
              Kp + (size_t)(kt*64 + lrow)*HD + lcb);
        cpa16(sbase + (ov + (uint32_t)lrow*TSTR + lcb)*2u,
              Vtp + (size_t)lrow*SEQ + kt*64 + lcb);
    };

    uint32_t qf[4][4];
    {
        const __half* q0 = Qp + (size_t)(qt*256 + wrow)*HD;
        #pragma unroll
        for (int j=0;j<4;j++){
            int c = j*16 + 2*t;
            qf[j][0] = *(const uint32_t*)(q0 + (size_t)(gid  )*HD + c);
            qf[j][1] = *(const uint32_t*)(q0 + (size_t)(gid+8)*HD + c);
            qf[j][2] = *(const uint32_t*)(q0 + (size_t)(gid  )*HD + c + 8);
            qf[j][3] = *(const uint32_t*)(q0 + (size_t)(gid+8)*HD + c + 8);
        }
    }

    load_kv(0, 0);
    CP_COMMIT(); CP_WAIT0();
    __syncthreads();

    float rs[2] = {0.f, 0.f};
    float o[8][4];
    #pragma unroll
    for (int dn=0;dn<8;dn++){ o[dn][0]=0;o[dn][1]=0;o[dn][2]=0;o[dn][3]=0; }

    for (int kt = 0; kt < SEQ/64; kt++){
        int cur = kt & 1;
        if (kt < SEQ/64 - 1){ load_kv(kt+1, cur^1); CP_COMMIT(); }

        const __half* sK = smh + (cur ? OFF_K1 : OFF_K0);
        const __half* sV = smh + (cur ? OFF_V1 : OFF_V0);

        #pragma unroll
        for (int c=0;c<2;c++){
            int cb = c*32;
            float s[4][4];
            #pragma unroll
            for (int nt=0;nt<4;nt++){ s[nt][0]=0;s[nt][1]=0;s[nt][2]=0;s[nt][3]=0; }
            #pragma unroll
            for (int j=0;j<4;j++){
                int kc = j*16 + 2*t;
                #pragma unroll
                for (int nt=0;nt<4;nt++){
                    const __half* kr = sK + (cb + nt*8 + gid)*TSTR + kc;
                    uint32_t b[2] = { *(const uint32_t*)kr, *(const uint32_t*)(kr+8) };
                    mma16(s[nt], qf[j], b);
                }
            }

            #pragma unroll
            for (int nt=0;nt<4;nt++){
                s[nt][0] = ex2(s[nt][0]); s[nt][1] = ex2(s[nt][1]);
                s[nt][2] = ex2(s[nt][2]); s[nt][3] = ex2(s[nt][3]);
                rs[0] += s[nt][0] + s[nt][1];
                rs[1] += s[nt][2] + s[nt][3];
            }
            uint32_t pa[2][4];
            #pragma unroll
            for (int jj=0;jj<2;jj++){
                pa[jj][0] = h2pack(s[2*jj  ][0], s[2*jj  ][1]);
                pa[jj][1] = h2pack(s[2*jj  ][2], s[2*jj  ][3]);
                pa[jj][2] = h2pack(s[2*jj+1][0], s[2*jj+1][1]);
                pa[jj][3] = h2pack(s[2*jj+1][2], s[2*jj+1][3]);
            }

            #pragma unroll
            for (int jj=0;jj<2;jj++){
                int kv0 = cb + jj*16 + 2*t;
                #pragma unroll
                for (int dn=0;dn<8;dn++){
                    const __half* vr = sV + (dn*8 + gid)*TSTR + kv0;
                    uint32_t b[2] = { *(const uint32_t*)vr, *(const uint32_t*)(vr+8) };
                    mma16(o[dn], pa[jj], b);
                }
            }
        }

        CP_WAIT0();
        __syncthreads();
    }

    #pragma unroll
    for (int k=0;k<2;k++){
        rs[k] += __shfl_xor_sync(0xffffffffu, rs[k], 1);
        rs[k] += __shfl_xor_sync(0xffffffffu, rs[k], 2);
    }

    // epilogue -> g_att fp16 in [B,S,E] (feeds the fp16 proj GEMM)
    float il0 = 1.f/rs[0], il1 = 1.f/rs[1];
    int b = bh / NH, h = bh % NH;
    int r0 = qt*256 + wrow + gid;
    __half* p0 = g_att + ((size_t)b*SEQ + r0)*EMB + h*HD;
    __half* p1 = p0 + (size_t)8*EMB;
    #pragma unroll
    for (int dn=0;dn<8;dn++){
        int d = dn*8 + 2*t;
        *(__half2*)&p0[d] = __floats2half2_rn(o[dn][0]*il0, o[dn][1]*il0);
        *(__half2*)&p1[d] = __floats2half2_rn(o[dn][2]*il1, o[dn][3]*il1);
    }
}

extern "C" void kernel_launch(void* const* d_in, const int* in_sizes, int n_in,
                              void* d_out, int out_size){
    (void)in_sizes; (void)n_in; (void)out_size;
    const float* x     = (const float*)d_in[0];
    const float* Wqkv  = (const float*)d_in[1];
    const float* Wproj = (const float*)d_in[2];
    const float* bproj = (const float*)d_in[3];
    float* out = (float*)d_out;

    __half *d_xh, *d_wq, *d_wp, *d_att;
    cudaGetSymbolAddress((void**)&d_xh,  g_xh);
    cudaGetSymbolAddress((void**)&d_wq,  g_wqh);
    cudaGetSymbolAddress((void**)&d_wp,  g_wph);
    cudaGetSymbolAddress((void**)&d_att, g_att);

    const int attn_smem = SM_HALFS * (int)sizeof(__half);  // 36864 B
    const int gemm_smem = 6*GCH * (int)sizeof(__half);     // 61440 B
    cudaFuncSetAttribute(attn_mma,     cudaFuncAttributeMaxDynamicSharedMemorySize, attn_smem);
    cudaFuncSetAttribute(gemm_fp16<0>, cudaFuncAttributeMaxDynamicSharedMemorySize, gemm_smem);
    cudaFuncSetAttribute(gemm_fp16<1>, cudaFuncAttributeMaxDynamicSharedMemorySize, gemm_smem);

    // 0) convert inputs to fp16
    to_fp16<<<(M_ROWS*EMB/4 + 255)/256, 256>>>(x,     d_xh, M_ROWS*EMB/4);
    to_fp16<<<(3*EMB*EMB/4  + 255)/256, 256>>>(Wqkv,  d_wq, 3*EMB*EMB/4);
    to_fp16<<<(EMB*EMB/4    + 255)/256, 256>>>(Wproj, d_wp, EMB*EMB/4);

    // 1) QKV projection (fp16 mma) -> fp16 Q/K (Q pre-scaled) + fp16 transposed V
    gemm_fp16<0><<<dim3(3*EMB/128, M_ROWS/128), 256, gemm_smem>>>(d_xh, d_wq, nullptr, nullptr);
    // 2) flash attention (fp16 mma, Q-in-regs)
    attn_mma<<<dim3(SEQ/256, BATCH*NH), 512, attn_smem>>>();
    // 3) output projection + bias (fp16 mma, fp32 out)
    gemm_fp16<1><<<dim3(EMB/128, M_ROWS/128), 256, gemm_smem>>>(d_att, d_wp, out, bproj);
}